// round 6
// baseline (speedup 1.0000x reference)
#include <cuda_runtime.h>
#include <math.h>

#define IMG_H 1080
#define IMG_W 1920
#define HW (IMG_H * IMG_W)

// Scratch (no cudaMalloc allowed). All statically zero-initialized at module
// load; norm_kernel restores the all-zeros state after every call, so every
// kernel_launch invocation sees the identical starting state (deterministic,
// no guards).
__device__ float4   g_buf4[HW];   // accumulated (r, g, b, z)
__device__ float    g_bufw[HW];   // accumulated weight
__device__ unsigned g_zbuf[HW];   // inverted z bits: key = ~float_bits(z); 0 == "empty" (z = +inf)

struct Proj {
    float r0x, r0y, r0z, t0;
    float r1x, r1y, r1z, t1;
    float r2x, r2y, r2z, t2;
    float fx, fy, cx, cy;
};

__device__ __forceinline__ Proj load_proj(const float* __restrict__ vm,
                                          const float* __restrict__ Km)
{
    Proj p;
    p.r0x = vm[0];  p.r0y = vm[1];  p.r0z = vm[2];  p.t0 = vm[3];
    p.r1x = vm[4];  p.r1y = vm[5];  p.r1z = vm[6];  p.t1 = vm[7];
    p.r2x = vm[8];  p.r2y = vm[9];  p.r2z = vm[10]; p.t2 = vm[11];
    p.fx = Km[0]; p.cx = Km[2]; p.fy = Km[4]; p.cy = Km[5];
    return p;
}

__device__ __forceinline__ bool project(const Proj& p,
                                        float mx, float my, float mz,
                                        float& x, float& y, float& z)
{
    z = p.r2x * mx + p.r2y * my + p.r2z * mz + p.t2;
    if (!(z > 0.1f)) return false;
    float cxm = p.r0x * mx + p.r0y * my + p.r0z * mz + p.t0;
    float cym = p.r1x * mx + p.r1y * my + p.r1z * mz + p.t1;
    x = cxm * p.fx / z + p.cx;
    y = cym * p.fy / z + p.cy;
    return (x >= 0.f) & (x < (float)(IMG_W - 1)) & (y >= 0.f) & (y < (float)(IMG_H - 1));
}

__device__ __forceinline__ float sigmoidf(float v) {
    return 1.f / (1.f + expf(-v));
}

// ---------------------------------------------------------------------------
// Pass 1: per-pixel z-min via atomicMax on inverted float bits.
// key(z) = ~float_bits(z) is strictly decreasing in z for z > 0, so max(key)
// selects min(z). Empty value 0 corresponds to z = +inf (NaN bits, never read
// for untouched pixels since splat only queries pixels this pass wrote).
// 4 points per thread via 3x float4 loads.
// ---------------------------------------------------------------------------
__global__ void zmin_kernel(const float4* __restrict__ means4,
                            const float* __restrict__ vm,
                            const float* __restrict__ Km, int n)
{
    int t = blockIdx.x * blockDim.x + threadIdx.x;
    int base = t * 4;
    if (base >= n) return;
    Proj p = load_proj(vm, Km);

    float mx[4], my[4], mz[4];
    if (base + 3 < n) {
        float4 a = means4[3 * t + 0];
        float4 b = means4[3 * t + 1];
        float4 c = means4[3 * t + 2];
        mx[0] = a.x; my[0] = a.y; mz[0] = a.z;
        mx[1] = a.w; my[1] = b.x; mz[1] = b.y;
        mx[2] = b.z; my[2] = b.w; mz[2] = c.x;
        mx[3] = c.y; my[3] = c.z; mz[3] = c.w;
    } else {
        const float* m = (const float*)means4;
        #pragma unroll
        for (int k = 0; k < 4; k++) {
            int i = base + k;
            if (i < n) { mx[k] = m[3*i]; my[k] = m[3*i+1]; mz[k] = m[3*i+2]; }
            else       { mx[k] = 0.f; my[k] = 0.f; mz[k] = -1.f; }
        }
    }

    #pragma unroll
    for (int k = 0; k < 4; k++) {
        float x, y, z;
        if (!project(p, mx[k], my[k], mz[k], x, y, z)) continue;
        int x0 = (int)floorf(x);
        int y0 = (int)floorf(y);
        atomicMax(&g_zbuf[y0 * IMG_W + x0], ~__float_as_uint(z));
    }
}

// ---------------------------------------------------------------------------
// Pass 2: visibility test + bilinear scatter of (sigmoid(rgb), z, w).
// 4 points per thread; colors loaded only for visible points.
// ---------------------------------------------------------------------------
__global__ void splat_kernel(const float4* __restrict__ means4,
                             const float* __restrict__ colors,
                             const float* __restrict__ vm,
                             const float* __restrict__ Km, int n)
{
    int t = blockIdx.x * blockDim.x + threadIdx.x;
    int base = t * 4;
    if (base >= n) return;
    Proj p = load_proj(vm, Km);

    float mx[4], my[4], mz[4];
    if (base + 3 < n) {
        float4 a = means4[3 * t + 0];
        float4 b = means4[3 * t + 1];
        float4 c = means4[3 * t + 2];
        mx[0] = a.x; my[0] = a.y; mz[0] = a.z;
        mx[1] = a.w; my[1] = b.x; mz[1] = b.y;
        mx[2] = b.z; my[2] = b.w; mz[2] = c.x;
        mx[3] = c.y; my[3] = c.z; mz[3] = c.w;
    } else {
        const float* m = (const float*)means4;
        #pragma unroll
        for (int k = 0; k < 4; k++) {
            int i = base + k;
            if (i < n) { mx[k] = m[3*i]; my[k] = m[3*i+1]; mz[k] = m[3*i+2]; }
            else       { mx[k] = 0.f; my[k] = 0.f; mz[k] = -1.f; }
        }
    }

    // Project all 4 (independent -> MLP on the zbuf loads below)
    float xs[4], ys[4], zs[4];
    bool on[4];
    int pix[4];
    float x0f[4], y0f[4];
    #pragma unroll
    for (int k = 0; k < 4; k++) {
        on[k] = project(p, mx[k], my[k], mz[k], xs[k], ys[k], zs[k]);
        x0f[k] = floorf(xs[k]);
        y0f[k] = floorf(ys[k]);
        pix[k] = on[k] ? ((int)y0f[k] * IMG_W + (int)x0f[k]) : 0;
    }

    unsigned zb[4];
    #pragma unroll
    for (int k = 0; k < 4; k++)
        if (on[k]) zb[k] = g_zbuf[pix[k]];

    #pragma unroll
    for (int k = 0; k < 4; k++) {
        if (!on[k]) continue;
        float zref = __uint_as_float(~zb[k]);
        float z = zs[k];
        if (!(z <= zref + 0.05f)) continue;

        float dx = xs[k] - x0f[k];
        float dy = ys[k] - y0f[k];
        float wa = (1.f - dx) * (1.f - dy);
        float wb = dx * (1.f - dy);
        float wc = (1.f - dx) * dy;
        float wd = dx * dy;

        int i = base + k;
        float r = sigmoidf(colors[3 * i]);
        float g = sigmoidf(colors[3 * i + 1]);
        float b = sigmoidf(colors[3 * i + 2]);

        int pa = pix[k];
        int pb = pa + IMG_W;      // (x0, y1): reference applies wb here
        int pc = pa + 1;          // (x1, y0): reference applies wc here
        int pd = pa + IMG_W + 1;  // (x1, y1)

        atomicAdd(&g_buf4[pa], make_float4(r * wa, g * wa, b * wa, z * wa));
        atomicAdd(&g_bufw[pa], wa);
        atomicAdd(&g_buf4[pb], make_float4(r * wb, g * wb, b * wb, z * wb));
        atomicAdd(&g_bufw[pb], wb);
        atomicAdd(&g_buf4[pc], make_float4(r * wc, g * wc, b * wc, z * wc));
        atomicAdd(&g_bufw[pc], wc);
        atomicAdd(&g_buf4[pd], make_float4(r * wd, g * wd, b * wd, z * wd));
        atomicAdd(&g_bufw[pd], wd);
    }
}

// ---------------------------------------------------------------------------
// Pass 3: normalize + write output, and restore scratch to all-zeros so the
// next invocation of kernel_launch sees the identical starting state.
// ---------------------------------------------------------------------------
__global__ void norm_kernel(float4* __restrict__ out)
{
    int i = blockIdx.x * blockDim.x + threadIdx.x;
    if (i >= HW) return;
    float4 acc = g_buf4[i];
    float w = g_bufw[i];

    // reset invariant
    g_buf4[i] = make_float4(0.f, 0.f, 0.f, 0.f);
    g_bufw[i] = 0.f;
    g_zbuf[i] = 0u;

    float inv = 1.f / (w + 1e-6f);
    float4 o;
    o.x = __saturatef(acc.x * inv);
    o.y = __saturatef(acc.y * inv);
    o.z = __saturatef(acc.z * inv);
    o.w = acc.w * inv;
    out[i] = o;
}

extern "C" void kernel_launch(void* const* d_in, const int* in_sizes, int n_in,
                              void* d_out, int out_size)
{
    const float* means  = (const float*)d_in[0];
    const float* colors = (const float*)d_in[1];
    // d_in[2] opacities, d_in[3] scales, d_in[4] quats: unused by reference output
    const float* vm = (const float*)d_in[5];
    const float* Km = (const float*)d_in[6];

    int n = in_sizes[0] / 3;
    int nt = (n + 3) / 4;  // 4 points per thread

    const int B = 256;
    zmin_kernel<<<(nt + B - 1) / B, B>>>((const float4*)means, vm, Km, n);
    splat_kernel<<<(nt + B - 1) / B, B>>>((const float4*)means, colors, vm, Km, n);
    norm_kernel<<<(HW + B - 1) / B, B>>>((float4*)d_out);
}

// round 11
// speedup vs baseline: 1.0021x; 1.0021x over previous
#include <cuda_runtime.h>
#include <math.h>

#define IMG_H 1080
#define IMG_W 1920
#define HW (IMG_H * IMG_W)

// Scratch (no cudaMalloc allowed). Statically zero-initialized at module load;
// norm_kernel restores the all-zeros state after every call, so every
// kernel_launch invocation sees the identical starting state.
__device__ float4   g_buf4[HW];   // accumulated (r, g, b, z)
__device__ float    g_bufw[HW];   // accumulated weight
__device__ unsigned g_zbuf[HW];   // inverted z bits: key = ~float_bits(z); 0 == "empty"

// EXACT arithmetic (matches reference bit-stability): plain /, expf.
__device__ __forceinline__ bool project(
    const float* __restrict__ vm, const float* __restrict__ Km,
    float mx, float my, float mz,
    float& x, float& y, float& z)
{
    z = vm[8] * mx + vm[9] * my + vm[10] * mz + vm[11];
    if (!(z > 0.1f)) return false;
    float cxm = vm[0] * mx + vm[1] * my + vm[2] * mz + vm[3];
    float cym = vm[4] * mx + vm[5] * my + vm[6] * mz + vm[7];
    float fx = Km[0], cx = Km[2], fy = Km[4], cy = Km[5];
    x = cxm * fx / z + cx;
    y = cym * fy / z + cy;
    return (x >= 0.f) & (x < (float)(IMG_W - 1)) & (y >= 0.f) & (y < (float)(IMG_H - 1));
}

__device__ __forceinline__ float sigmoidf(float v) {
    return 1.f / (1.f + expf(-v));
}

// ---------------------------------------------------------------------------
// Pass 1: per-pixel z-min via atomicMax on inverted float bits.
// key(z) = ~float_bits(z) is strictly decreasing in z for z > 0, so max(key)
// selects exactly the same winner as atomicMin on the raw bits. Empty value 0
// corresponds to z = +inf; untouched pixels are never queried by splat.
// ---------------------------------------------------------------------------
__global__ void zmin_kernel(const float* __restrict__ means,
                            const float* __restrict__ vm,
                            const float* __restrict__ Km, int n)
{
    int i = blockIdx.x * blockDim.x + threadIdx.x;
    if (i >= n) return;
    float mx = means[3 * i], my = means[3 * i + 1], mz = means[3 * i + 2];
    float x, y, z;
    if (!project(vm, Km, mx, my, mz, x, y, z)) return;
    int x0 = (int)floorf(x);
    int y0 = (int)floorf(y);
    atomicMax(&g_zbuf[y0 * IMG_W + x0], ~__float_as_uint(z));
}

// ---------------------------------------------------------------------------
// Pass 2: visibility test + bilinear scatter of (sigmoid(rgb), z, w).
// ---------------------------------------------------------------------------
__global__ void splat_kernel(const float* __restrict__ means,
                             const float* __restrict__ colors,
                             const float* __restrict__ vm,
                             const float* __restrict__ Km, int n)
{
    int i = blockIdx.x * blockDim.x + threadIdx.x;
    if (i >= n) return;
    float mx = means[3 * i], my = means[3 * i + 1], mz = means[3 * i + 2];
    float x, y, z;
    if (!project(vm, Km, mx, my, mz, x, y, z)) return;

    float x0f = floorf(x), y0f = floorf(y);
    int x0 = (int)x0f, y0 = (int)y0f;
    int pix = y0 * IMG_W + x0;

    float zref = __uint_as_float(~g_zbuf[pix]);
    if (!(z <= zref + 0.05f)) return;

    float dx = x - x0f, dy = y - y0f;
    float wa = (1.f - dx) * (1.f - dy);
    float wb = dx * (1.f - dy);
    float wc = (1.f - dx) * dy;
    float wd = dx * dy;

    float r = sigmoidf(colors[3 * i]);
    float g = sigmoidf(colors[3 * i + 1]);
    float b = sigmoidf(colors[3 * i + 2]);

    int pb = pix + IMG_W;      // (x0, y1): reference applies wb here
    int pc = pix + 1;          // (x1, y0): reference applies wc here
    int pd = pix + IMG_W + 1;  // (x1, y1)

    atomicAdd(&g_buf4[pix], make_float4(r * wa, g * wa, b * wa, z * wa));
    atomicAdd(&g_bufw[pix], wa);
    atomicAdd(&g_buf4[pb],  make_float4(r * wb, g * wb, b * wb, z * wb));
    atomicAdd(&g_bufw[pb],  wb);
    atomicAdd(&g_buf4[pc],  make_float4(r * wc, g * wc, b * wc, z * wc));
    atomicAdd(&g_bufw[pc],  wc);
    atomicAdd(&g_buf4[pd],  make_float4(r * wd, g * wd, b * wd, z * wd));
    atomicAdd(&g_bufw[pd],  wd);
}

// ---------------------------------------------------------------------------
// Pass 3: normalize + write output, and restore scratch to all-zeros so the
// next invocation of kernel_launch sees the identical starting state.
// ---------------------------------------------------------------------------
__global__ void norm_kernel(float4* __restrict__ out)
{
    int i = blockIdx.x * blockDim.x + threadIdx.x;
    if (i >= HW) return;
    float4 acc = g_buf4[i];
    float w = g_bufw[i];

    // reset invariant for next invocation
    g_buf4[i] = make_float4(0.f, 0.f, 0.f, 0.f);
    g_bufw[i] = 0.f;
    g_zbuf[i] = 0u;

    float inv = 1.f / (w + 1e-6f);   // exact division
    float4 o;
    o.x = __saturatef(acc.x * inv);
    o.y = __saturatef(acc.y * inv);
    o.z = __saturatef(acc.z * inv);
    o.w = acc.w * inv;
    out[i] = o;
}

extern "C" void kernel_launch(void* const* d_in, const int* in_sizes, int n_in,
                              void* d_out, int out_size)
{
    const float* means  = (const float*)d_in[0];
    const float* colors = (const float*)d_in[1];
    // d_in[2] opacities, d_in[3] scales, d_in[4] quats: unused by reference output
    const float* vm = (const float*)d_in[5];
    const float* Km = (const float*)d_in[6];

    int n = in_sizes[0] / 3;

    const int B = 256;
    zmin_kernel<<<(n + B - 1) / B, B>>>(means, vm, Km, n);
    splat_kernel<<<(n + B - 1) / B, B>>>(means, colors, vm, Km, n);
    norm_kernel<<<(HW + B - 1) / B, B>>>((float4*)d_out);
}

// round 12
// speedup vs baseline: 1.0047x; 1.0026x over previous
#include <cuda_runtime.h>
#include <math.h>

#define IMG_H 1080
#define IMG_W 1920
#define HW (IMG_H * IMG_W)
#define HW4 (HW / 4)

// Scratch (no cudaMalloc allowed)
__device__ float4   g_buf4[HW];   // accumulated (r, g, b, z)
__device__ float    g_bufw[HW];   // accumulated weight
__device__ unsigned g_zbuf[HW];   // z-buffer bits (positive floats: order-preserving)

// ---------------------------------------------------------------------------
// Init: explicit, immediately before the atomic passes. This both initializes
// AND warms the accumulator / z-buffer lines in L2 — removing it (reset at the
// end of the previous call) measured +43us on the atomic passes.
// Vectorized 16B stores, coalesced mapping.
// ---------------------------------------------------------------------------
__global__ void init_kernel() {
    int i = blockIdx.x * blockDim.x + threadIdx.x;
    if (i >= HW4) return;
    const float4 z4 = make_float4(0.f, 0.f, 0.f, 0.f);
    ((float4*)g_bufw)[i] = z4;
    ((uint4*)g_zbuf)[i] = make_uint4(0x7f800000u, 0x7f800000u, 0x7f800000u, 0x7f800000u);
    g_buf4[i]           = z4;
    g_buf4[i + HW4]     = z4;
    g_buf4[i + 2*HW4]   = z4;
    g_buf4[i + 3*HW4]   = z4;
}

// EXACT arithmetic (discrete decisions downstream: floor, z-compare).
__device__ __forceinline__ bool project(
    const float* __restrict__ vm, const float* __restrict__ Km,
    float mx, float my, float mz,
    float& x, float& y, float& z)
{
    z = vm[8] * mx + vm[9] * my + vm[10] * mz + vm[11];
    if (!(z > 0.1f)) return false;
    float cxm = vm[0] * mx + vm[1] * my + vm[2] * mz + vm[3];
    float cym = vm[4] * mx + vm[5] * my + vm[6] * mz + vm[7];
    float fx = Km[0], cx = Km[2], fy = Km[4], cy = Km[5];
    x = cxm * fx / z + cx;
    y = cym * fy / z + cy;
    return (x >= 0.f) & (x < (float)(IMG_W - 1)) & (y >= 0.f) & (y < (float)(IMG_H - 1));
}

__device__ __forceinline__ float sigmoidf(float v) {
    return 1.f / (1.f + expf(-v));
}

// ---------------------------------------------------------------------------
// Pass 1: per-pixel z-min via atomicMin on float bits (all z > 0.1 > 0, so
// uint compare == float compare).
// ---------------------------------------------------------------------------
__global__ void zmin_kernel(const float* __restrict__ means,
                            const float* __restrict__ vm,
                            const float* __restrict__ Km, int n)
{
    int i = blockIdx.x * blockDim.x + threadIdx.x;
    if (i >= n) return;
    float mx = means[3 * i], my = means[3 * i + 1], mz = means[3 * i + 2];
    float x, y, z;
    if (!project(vm, Km, mx, my, mz, x, y, z)) return;
    int x0 = (int)floorf(x);
    int y0 = (int)floorf(y);
    atomicMin(&g_zbuf[y0 * IMG_W + x0], __float_as_uint(z));
}

// ---------------------------------------------------------------------------
// Pass 2: visibility test + bilinear scatter of (sigmoid(rgb), z, w).
// ---------------------------------------------------------------------------
__global__ void splat_kernel(const float* __restrict__ means,
                             const float* __restrict__ colors,
                             const float* __restrict__ vm,
                             const float* __restrict__ Km, int n)
{
    int i = blockIdx.x * blockDim.x + threadIdx.x;
    if (i >= n) return;
    float mx = means[3 * i], my = means[3 * i + 1], mz = means[3 * i + 2];
    float x, y, z;
    if (!project(vm, Km, mx, my, mz, x, y, z)) return;

    float x0f = floorf(x), y0f = floorf(y);
    int x0 = (int)x0f, y0 = (int)y0f;
    int pix = y0 * IMG_W + x0;

    float zref = __uint_as_float(g_zbuf[pix]);
    if (!(z <= zref + 0.05f)) return;

    float dx = x - x0f, dy = y - y0f;
    float wa = (1.f - dx) * (1.f - dy);
    float wb = dx * (1.f - dy);
    float wc = (1.f - dx) * dy;
    float wd = dx * dy;

    float r = sigmoidf(colors[3 * i]);
    float g = sigmoidf(colors[3 * i + 1]);
    float b = sigmoidf(colors[3 * i + 2]);

    int pb = pix + IMG_W;      // (x0, y1): reference applies wb here
    int pc = pix + 1;          // (x1, y0): reference applies wc here
    int pd = pix + IMG_W + 1;  // (x1, y1)

    atomicAdd(&g_buf4[pix], make_float4(r * wa, g * wa, b * wa, z * wa));
    atomicAdd(&g_bufw[pix], wa);
    atomicAdd(&g_buf4[pb],  make_float4(r * wb, g * wb, b * wb, z * wb));
    atomicAdd(&g_bufw[pb],  wb);
    atomicAdd(&g_buf4[pc],  make_float4(r * wc, g * wc, b * wc, z * wc));
    atomicAdd(&g_bufw[pc],  wc);
    atomicAdd(&g_buf4[pd],  make_float4(r * wd, g * wd, b * wd, z * wd));
    atomicAdd(&g_bufw[pd],  wd);
}

// ---------------------------------------------------------------------------
// Pass 3: normalize + write output (no resets — init handles state).
// ---------------------------------------------------------------------------
__global__ void norm_kernel(float4* __restrict__ out)
{
    int i = blockIdx.x * blockDim.x + threadIdx.x;
    if (i >= HW) return;
    float4 acc = g_buf4[i];
    float inv = 1.f / (g_bufw[i] + 1e-6f);
    float4 o;
    o.x = __saturatef(acc.x * inv);
    o.y = __saturatef(acc.y * inv);
    o.z = __saturatef(acc.z * inv);
    o.w = acc.w * inv;
    out[i] = o;
}

extern "C" void kernel_launch(void* const* d_in, const int* in_sizes, int n_in,
                              void* d_out, int out_size)
{
    const float* means  = (const float*)d_in[0];
    const float* colors = (const float*)d_in[1];
    // d_in[2] opacities, d_in[3] scales, d_in[4] quats: unused by reference output
    const float* vm = (const float*)d_in[5];
    const float* Km = (const float*)d_in[6];

    int n = in_sizes[0] / 3;

    const int B = 256;
    init_kernel<<<(HW4 + B - 1) / B, B>>>();
    zmin_kernel<<<(n + B - 1) / B, B>>>(means, vm, Km, n);
    splat_kernel<<<(n + B - 1) / B, B>>>(means, colors, vm, Km, n);
    norm_kernel<<<(HW + B - 1) / B, B>>>((float4*)d_out);
}